// round 14
// baseline (speedup 1.0000x reference)
#include <cuda_runtime.h>
#include <cuda_fp16.h>
#include <cstdint>

#define Bc   2
#define Sc   2048
#define DIMc 1024
#define NHc  16
#define HDc  64
#define TTOT (Bc*Sc)
#define CHUNK (TTOT*DIMc)          // 4,194,304 elements

// Scratch arena (fp16), CHUNK units: 0 X | 1 W(4 mats) | 2 Q | 3 K | 4 V | 5 C
__device__ __half g_buf[6ull * CHUNK];

// ---------------------------------------------------------------------------
// helpers
// ---------------------------------------------------------------------------
__device__ __forceinline__ unsigned sptr(const void* p) {
    return (unsigned)__cvta_generic_to_shared(p);
}
__device__ __forceinline__ void cpa16(unsigned d, const void* s) {
    asm volatile("cp.async.cg.shared.global [%0], [%1], 16;" :: "r"(d), "l"(s));
}
__device__ __forceinline__ void cp_commit() { asm volatile("cp.async.commit_group;"); }
__device__ __forceinline__ void cp_wait0()  { asm volatile("cp.async.wait_group 0;"); }
__device__ __forceinline__ void cp_wait1()  { asm volatile("cp.async.wait_group 1;"); }

__device__ __forceinline__ void ldsm4(unsigned a, unsigned* r) {
    asm volatile("ldmatrix.sync.aligned.m8n8.x4.shared.b16 {%0,%1,%2,%3},[%4];"
        : "=r"(r[0]), "=r"(r[1]), "=r"(r[2]), "=r"(r[3]) : "r"(a));
}
__device__ __forceinline__ void ldsm4t(unsigned a, unsigned* r) {
    asm volatile("ldmatrix.sync.aligned.m8n8.x4.trans.shared.b16 {%0,%1,%2,%3},[%4];"
        : "=r"(r[0]), "=r"(r[1]), "=r"(r[2]), "=r"(r[3]) : "r"(a));
}
__device__ __forceinline__ void mma_f16(float* c, const unsigned* a, unsigned b0, unsigned b1) {
    asm volatile(
        "mma.sync.aligned.m16n8k16.row.col.f32.f16.f16.f32 "
        "{%0,%1,%2,%3},{%4,%5,%6,%7},{%8,%9},{%0,%1,%2,%3};"
        : "+f"(c[0]), "+f"(c[1]), "+f"(c[2]), "+f"(c[3])
        : "r"(a[0]), "r"(a[1]), "r"(a[2]), "r"(a[3]), "r"(b0), "r"(b1));
}
__device__ __forceinline__ unsigned packh2(float v0, float v1) {
    unsigned r;
    asm("cvt.rn.f16x2.f32 %0, %1, %2;" : "=r"(r) : "f"(v1), "f"(v0));
    return r;
}
__device__ __forceinline__ void stcs2(float* p, float a, float b) {
    asm volatile("st.global.cs.v2.f32 [%0], {%1,%2};" :: "l"(p), "f"(a), "f"(b));
}
__device__ __forceinline__ void stcs4(float* p, float a, float b, float c, float d) {
    asm volatile("st.global.cs.v4.f32 [%0], {%1,%2,%3,%4};"
                 :: "l"(p), "f"(a), "f"(b), "f"(c), "f"(d));
}

// ---------------------------------------------------------------------------
// One-time convert: x + 4 weight matrices -> fp16
// ---------------------------------------------------------------------------
__global__ void cvt_all(const float* __restrict__ x,
                        const float* __restrict__ wq, const float* __restrict__ wk,
                        const float* __restrict__ wv, const float* __restrict__ wo,
                        __half* __restrict__ X, __half* __restrict__ W)
{
    int i = blockIdx.x * blockDim.x + threadIdx.x;
    const int NX = CHUNK / 4;
    const int NW = (DIMc * DIMc) / 4;
    const float* src; __half* dst; int idx;
    if (i < NX) { src = x; dst = X; idx = i; }
    else {
        int j = i - NX;
        if (j >= 4 * NW) return;
        int m = j >> 18; idx = j & (NW - 1);
        src = (m == 0) ? wq : (m == 1) ? wk : (m == 2) ? wv : wo;
        dst = W + (size_t)m * DIMc * DIMc;
    }
    float4 v = reinterpret_cast<const float4*>(src)[idx];
    reinterpret_cast<uint2*>(dst)[idx] = make_uint2(packh2(v.x, v.y), packh2(v.z, v.w));
}

// ---------------------------------------------------------------------------
// Projection GEMM (fp16): BM=BN=128, BK=64, 3-stage cp.async, 256 thr, 2/SM.
// MODE 1: z-fused QKV (z<2 -> rope), fp16 out. MODE 0: fp32 out (.cs).
// ---------------------------------------------------------------------------
#define SPp   72            // smem row stride (halfs): 144B, LDSM conflict-free
#define PBUFp (128*SPp)     // 9216 halfs per matrix buffer

template<int MODE>
__global__ __launch_bounds__(256, 2) void proj_mma(
    const __half* __restrict__ A_g, const __half* __restrict__ WBase,
    float* __restrict__ OutF, __half* __restrict__ OBase,
    const float* __restrict__ fc, const float* __restrict__ fs)
{
    extern __shared__ __align__(16) __half ps[];   // 3 stages x 2 bufs x PBUFp

    const int tid = threadIdx.x;
    const int warp = tid >> 5, lane = tid & 31;
    const int g = lane >> 3, r7 = lane & 7;
    const int mBase = blockIdx.y * 128, nBase = blockIdx.x * 128;
    const int z = blockIdx.z;
    const __half* W_g = WBase + (size_t)z * DIMc * DIMc;
    const int wm = (warp & 3) * 32, wn = (warp >> 2) * 64;

    float c[2][8][4];
    #pragma unroll
    for (int i = 0; i < 2; i++)
        #pragma unroll
        for (int j = 0; j < 8; j++)
            #pragma unroll
            for (int k = 0; k < 4; k++) c[i][j][k] = 0.f;

    auto pload = [&](int slot, int t) {
        __half* base = ps + slot * 2 * PBUFp;
        int k0 = t * 64;
        #pragma unroll
        for (int i = 0; i < 4; i++) {
            int ch = tid + 256 * i;
            int r = ch >> 3, c8 = (ch & 7) * 8;
            cpa16(sptr(&base[r*SPp + c8]), &A_g[(size_t)(mBase + r) * DIMc + k0 + c8]);
            cpa16(sptr(&base[PBUFp + r*SPp + c8]), &W_g[(size_t)(nBase + r) * DIMc + k0 + c8]);
        }
    };

    pload(0, 0); cp_commit();
    pload(1, 1); cp_commit();

    for (int t = 0; t < 16; t++) {
        int cur = t % 3;
        if (t < 15) cp_wait1(); else cp_wait0();
        __syncthreads();
        if (t + 2 <= 15) { pload((t + 2) % 3, t + 2); cp_commit(); }

        __half* Ah = ps + cur * 2 * PBUFp;
        __half* Bh = Ah + PBUFp;

        #pragma unroll
        for (int kk = 0; kk < 64; kk += 16) {
            unsigned ah[2][4];
            #pragma unroll
            for (int mt = 0; mt < 2; mt++) {
                int row = wm + mt*16 + (g & 1)*8 + r7;
                int col = kk + (g >> 1)*8;
                ldsm4(sptr(&Ah[row*SPp + col]), ah[mt]);
            }
            #pragma unroll
            for (int np = 0; np < 4; np++) {
                int row = wn + np*16 + (g >> 1)*8 + r7;
                int col = kk + (g & 1)*8;
                unsigned bh[4];
                ldsm4(sptr(&Bh[row*SPp + col]), bh);
                mma_f16(c[0][np*2],   ah[0], bh[0], bh[1]);
                mma_f16(c[0][np*2+1], ah[0], bh[2], bh[3]);
                mma_f16(c[1][np*2],   ah[1], bh[0], bh[1]);
                mma_f16(c[1][np*2+1], ah[1], bh[2], bh[3]);
            }
        }
    }

    __half* O_g = (MODE == 1) ? OBase + (size_t)z * CHUNK : nullptr;
    const bool doRope = (MODE == 1) && (z < 2);

    #pragma unroll
    for (int mt = 0; mt < 2; mt++) {
        int row = mBase + wm + mt*16 + (lane >> 2);
        #pragma unroll
        for (int nt = 0; nt < 8; nt++) {
            int col = nBase + wn + nt*8 + (lane & 3)*2;
            float v0 = c[mt][nt][0], v1 = c[mt][nt][1];
            float v2 = c[mt][nt][2], v3 = c[mt][nt][3];
            if (doRope) {
                int i = (col & 63) >> 1;
                int s0 = row & (Sc-1), s1 = (row + 8) & (Sc-1);
                float c0 = fc[s0*32 + i], sn0 = fs[s0*32 + i];
                float c1 = fc[s1*32 + i], sn1 = fs[s1*32 + i];
                float a0 = v0, b0 = v1, a1 = v2, b1 = v3;
                v0 = a0*c0 - b0*sn0; v1 = a0*sn0 + b0*c0;
                v2 = a1*c1 - b1*sn1; v3 = a1*sn1 + b1*c1;
            }
            if (MODE == 0) {
                stcs2(OutF + (size_t)row * DIMc + col,     v0, v1);
                stcs2(OutF + (size_t)(row+8) * DIMc + col, v2, v3);
            } else {
                *(unsigned*)&O_g[(size_t)row * DIMc + col]     = packh2(v0, v1);
                *(unsigned*)&O_g[(size_t)(row+8) * DIMc + col] = packh2(v2, v3);
            }
        }
    }
}

// ---------------------------------------------------------------------------
// Attention (fp16): 64-row q-blocks, 256 threads (8 warps), 2 CTAs/SM.
// Warp layout: m16 x n64 (4 m-groups x 2 k-slice groups).
// Pass 1: QK -> exp in regs -> C-frag->A-frag -> partial PV per k-slice;
// end-of-pass smem reduction (aliases dead V buffer).
// Pass 2: 3-stage K pipeline (stage 2 reuses V buffer), recompute scores,
// write normalized weights via 16B .cs stores (shfl-paired).
// ---------------------------------------------------------------------------
#define SQa 72
#define QB64 (64*SQa)     // 4608 halfs (Q tile)
#define KB   (128*SQa)    // 9216 halfs (K/V tiles)

__global__ __launch_bounds__(256, 2) void attn_mma(
    float* __restrict__ attn,
    const __half* __restrict__ Q_g, const __half* __restrict__ K_g,
    const __half* __restrict__ V_g, __half* __restrict__ C_g)
{
    extern __shared__ __align__(16) __half sm[];
    __half* Qh = sm;                 // QB64
    __half* Kst = Qh + QB64;         // pass1: 2 stages; pass2: 3 stages (incl V slot)
    __half* Vh = Kst + 2*KB;         // KB (== Kst stage 2 in pass 2)
    float* rowsum = (float*)(Vh + KB);      // 64 floats
    float* red = (float*)Vh;                // 64x65 fp32, aliases dead V buffer

    const int tid = threadIdx.x;
    const int warp = tid >> 5, lane = tid & 31;
    const int g = lane >> 3, r7 = lane & 7;
    const int qBase = blockIdx.x * 64;
    const int h = blockIdx.y, b = blockIdx.z;

    const size_t qOff = (size_t)(b * Sc + qBase) * DIMc + h * HDc;
    const size_t kvOff = (size_t)b * Sc * DIMc + h * HDc;
    float* arow = attn + ((size_t)(b * NHc + h) * Sc + qBase) * Sc;

    if (tid < 64) rowsum[tid] = 0.f;

    auto kload = [&](int s, int kt) {
        __half* KH = Kst + s * KB;
        #pragma unroll
        for (int i = 0; i < 4; i++) {
            int ch = tid + 256 * i;
            int r = ch >> 3, c8 = (ch & 7) * 8;
            cpa16(sptr(&KH[r*SQa + c8]), &K_g[kvOff + (size_t)(kt + r) * DIMc + c8]);
        }
    };
    auto vload = [&](int kt) {
        #pragma unroll
        for (int i = 0; i < 4; i++) {
            int ch = tid + 256 * i;
            int r = ch >> 3, c8 = (ch & 7) * 8;
            cpa16(sptr(&Vh[r*SQa + c8]), &V_g[kvOff + (size_t)(kt + r) * DIMc + c8]);
        }
    };

    #pragma unroll
    for (int i = 0; i < 2; i++) {
        int ch = tid + 256 * i;
        int r = ch >> 3, c8 = (ch & 7) * 8;
        cpa16(sptr(&Qh[r*SQa + c8]), &Q_g[qOff + (size_t)r * DIMc + c8]);
    }
    kload(0, 0);
    cp_commit();

    const int wm = (warp & 3) * 16;     // m offset (16 rows per warp)
    const int wk = (warp >> 2) * 64;    // key-slice offset (64 keys per warp)

    float ctx[8][4];
    #pragma unroll
    for (int i = 0; i < 8; i++)
        #pragma unroll
        for (int j = 0; j < 4; j++) ctx[i][j] = 0.f;
    float rs0 = 0.f, rs1 = 0.f;

    // ---------------- pass 1 ----------------
    for (int t = 0; t < Sc / 128; t++) {
        const int cur = t & 1;
        cp_wait0();
        __syncthreads();                 // K_t visible; V slot free
        vload(t * 128); cp_commit();
        const bool pre = (t + 1 < Sc / 128);
        if (pre) { kload(cur ^ 1, (t + 1) * 128); cp_commit(); }

        __half* KH = Kst + cur * KB;

        float s[8][4];
        #pragma unroll
        for (int i = 0; i < 8; i++)
            #pragma unroll
            for (int j = 0; j < 4; j++) s[i][j] = 0.f;
        #pragma unroll
        for (int kk = 0; kk < 64; kk += 16) {
            unsigned ah[4];
            ldsm4(sptr(Qh + (wm + (g & 1)*8 + r7)*SQa + kk + (g >> 1)*8), ah);
            #pragma unroll
            for (int np = 0; np < 4; np++) {
                unsigned bh[4];
                ldsm4(sptr(KH + (wk + np*16 + (g >> 1)*8 + r7)*SQa + kk + (g & 1)*8), bh);
                mma_f16(s[np*2],   ah, bh[0], bh[1]);
                mma_f16(s[np*2+1], ah, bh[2], bh[3]);
            }
        }

        if (pre) cp_wait1(); else cp_wait0();   // V_t arrived
        __syncthreads();

        #pragma unroll
        for (int nt = 0; nt < 8; nt++) {
            s[nt][0] = __expf(s[nt][0] * 0.125f);
            s[nt][1] = __expf(s[nt][1] * 0.125f);
            s[nt][2] = __expf(s[nt][2] * 0.125f);
            s[nt][3] = __expf(s[nt][3] * 0.125f);
            rs0 += s[nt][0] + s[nt][1];
            rs1 += s[nt][2] + s[nt][3];
        }

        #pragma unroll
        for (int kc = 0; kc < 4; kc++) {
            unsigned a[4];
            a[0] = packh2(s[kc*2][0],   s[kc*2][1]);
            a[1] = packh2(s[kc*2][2],   s[kc*2][3]);
            a[2] = packh2(s[kc*2+1][0], s[kc*2+1][1]);
            a[3] = packh2(s[kc*2+1][2], s[kc*2+1][3]);
            int vrow = wk + kc*16 + (g & 1)*8 + r7;
            #pragma unroll
            for (int dp = 0; dp < 4; dp++) {
                unsigned bh[4];
                ldsm4t(sptr(Vh + vrow*SQa + dp*16 + (g >> 1)*8), bh);
                mma_f16(ctx[dp*2],   a, bh[0], bh[1]);
                mma_f16(ctx[dp*2+1], a, bh[2], bh[3]);
            }
        }
    }

    atomicAdd(&rowsum[wm + (lane >> 2)],     rs0);
    atomicAdd(&rowsum[wm + 8 + (lane >> 2)], rs1);
    __syncthreads();                      // PV done (Vh dead), atomics visible

    if (tid < 64) rowsum[tid] = 1.0f / rowsum[tid];
    if (warp < 4) {
        int r0 = wm + (lane >> 2);
        #pragma unroll
        for (int dt = 0; dt < 8; dt++) {
            int cc = dt*8 + (lane & 3)*2;
            red[r0*65 + cc]       = ctx[dt][0];
            red[r0*65 + cc + 1]   = ctx[dt][1];
            red[(r0+8)*65 + cc]   = ctx[dt][2];
            red[(r0+8)*65 + cc+1] = ctx[dt][3];
        }
    }
    __syncthreads();
    if (warp >= 4) {
        int r0 = wm + (lane >> 2);
        #pragma unroll
        for (int dt = 0; dt < 8; dt++) {
            int cc = dt*8 + (lane & 3)*2;
            red[r0*65 + cc]       += ctx[dt][0];
            red[r0*65 + cc + 1]   += ctx[dt][1];
            red[(r0+8)*65 + cc]   += ctx[dt][2];
            red[(r0+8)*65 + cc+1] += ctx[dt][3];
        }
    }
    __syncthreads();

    // prefetch pass-2 K_0, K_1 into stages 0,1 (NOT the red region) while
    // storing ctx
    kload(0, 0); cp_commit();
    kload(1, 128); cp_commit();

    #pragma unroll
    for (int i = 0; i < 8; i++) {
        int p = tid + 256 * i;
        int row = p >> 5;
        int cc = (p & 31) * 2;
        float iv = rowsum[row];
        *(unsigned*)&C_g[qOff + (size_t)row * DIMc + cc] =
            packh2(red[row*65 + cc] * iv, red[row*65 + cc + 1] * iv);
    }

    const float iv0 = rowsum[wm + (lane >> 2)];
    const float iv1 = rowsum[wm + 8 + (lane >> 2)];
    __syncthreads();   // all red/rowsum reads done before stage-2 kload hits it

    // ---------------- pass 2: 3-stage pipeline, recompute, v4 stores --------
    const int jq = lane & 3;
    for (int t = 0; t < Sc / 128; t++) {
        const int cur = t % 3;
        const int kt = t * 128;
        if (t < Sc/128 - 1) cp_wait1(); else cp_wait0();   // K_t ready
        __syncthreads();
        if (t + 2 <= Sc/128 - 1) { kload((t + 2) % 3, kt + 256); cp_commit(); }

        __half* KH = Kst + cur * KB;

        float s[8][4];
        #pragma unroll
        for (int i = 0; i < 8; i++)
            #pragma unroll
            for (int j = 0; j < 4; j++) s[i][j] = 0.f;
        #pragma unroll
        for (int kk = 0; kk < 64; kk += 16) {
            unsigned ah[4];
            ldsm4(sptr(Qh + (wm + (g & 1)*8 + r7)*SQa + kk + (g >> 1)*8), ah);
            #pragma unroll
            for (int np = 0; np < 4; np++) {
                unsigned bh[4];
                ldsm4(sptr(KH + (wk + np*16 + (g >> 1)*8 + r7)*SQa + kk + (g & 1)*8), bh);
                mma_f16(s[np*2],   ah, bh[0], bh[1]);
                mma_f16(s[np*2+1], ah, bh[2], bh[3]);
            }
        }

        int row0 = wm + (lane >> 2);
        #pragma unroll
        for (int nt = 0; nt < 8; nt++) {
            float e0 = __expf(s[nt][0] * 0.125f) * iv0;
            float e1 = __expf(s[nt][1] * 0.125f) * iv0;
            float e2 = __expf(s[nt][2] * 0.125f) * iv1;
            float e3 = __expf(s[nt][3] * 0.125f) * iv1;
            // pair with lane^1 to form 16B stores
            float f0 = __shfl_xor_sync(0xffffffffu, e0, 1);
            float f1 = __shfl_xor_sync(0xffffffffu, e1, 1);
            float f2 = __shfl_xor_sync(0xffffffffu, e2, 1);
            float f3 = __shfl_xor_sync(0xffffffffu, e3, 1);
            if (!(jq & 1)) {
                // even lane: row0, cols 2j..2j+3 (own e0,e1 + partner f0,f1)
                stcs4(arow + (size_t)row0 * Sc + kt + wk + nt*8 + 2*jq,
                      e0, e1, f0, f1);
            } else {
                // odd lane: row0+8, cols 2(j-1)..2(j-1)+3 (partner f2,f3 + own e2,e3)
                stcs4(arow + (size_t)(row0+8) * Sc + kt + wk + nt*8 + 2*(jq-1),
                      f2, f3, e2, e3);
            }
        }
    }
}

// ---------------------------------------------------------------------------
// Launcher
// ---------------------------------------------------------------------------
extern "C" void kernel_launch(void* const* d_in, const int* in_sizes, int n_in,
                              void* d_out, int out_size)
{
    const float* x  = (const float*)d_in[0];
    const float* wq = (const float*)d_in[1];
    const float* wk = (const float*)d_in[2];
    const float* wv = (const float*)d_in[3];
    const float* wo = (const float*)d_in[4];
    const float* fc = (const float*)d_in[5];
    const float* fs = (const float*)d_in[6];

    float* out  = (float*)d_out;
    float* attn = out + (size_t)Bc * Sc * DIMc;

    __half* buf;
    cudaGetSymbolAddress((void**)&buf, g_buf);
    const size_t WM = (size_t)DIMc * DIMc;
    __half* X = buf;
    __half* W = buf + 1ull*CHUNK;
    __half* Q = buf + 2ull*CHUNK;    // Q,K,V contiguous (z-indexed)
    __half* C = buf + 5ull*CHUNK;

    const int projSmem = 3 * 2 * PBUFp * 2;                 // 110,592 B
    cudaFuncSetAttribute(proj_mma<0>, cudaFuncAttributeMaxDynamicSharedMemorySize, projSmem);
    cudaFuncSetAttribute(proj_mma<1>, cudaFuncAttributeMaxDynamicSharedMemorySize, projSmem);
    const int attnSmem = (QB64 + 3*KB) * 2 + 64 * 4;        // 64,768 B
    cudaFuncSetAttribute(attn_mma, cudaFuncAttributeMaxDynamicSharedMemorySize, attnSmem);

    int nCvt = CHUNK / 4 + DIMc * DIMc;
    cvt_all<<<(nCvt + 255) / 256, 256>>>(x, wq, wk, wv, wo, X, W);

    // fused QKV (z=0 Q rope, z=1 K rope, z=2 V)
    proj_mma<1><<<dim3(DIMc/128, TTOT/128, 3), 256, projSmem>>>(X, W, nullptr, Q, fc, fs);

    attn_mma<<<dim3(Sc/64, NHc, Bc), 256, attnSmem>>>(attn, Q, Q + 1ull*CHUNK, Q + 2ull*CHUNK, C);

    proj_mma<0><<<dim3(DIMc/128, TTOT/128, 1), 256, projSmem>>>(C, W + 3*WM, out, nullptr, nullptr, nullptr);
}

// round 15
// speedup vs baseline: 1.0806x; 1.0806x over previous
#include <cuda_runtime.h>
#include <cuda_fp16.h>
#include <cstdint>

#define Bc   2
#define Sc   2048
#define DIMc 1024
#define NHc  16
#define HDc  64
#define TTOT (Bc*Sc)
#define CHUNK (TTOT*DIMc)          // 4,194,304 elements

// Scratch arena (fp16), CHUNK units: 0 X | 1 W(4 mats) | 2 Q | 3 K | 4 V | 5 C
__device__ __half g_buf[6ull * CHUNK];

// ---------------------------------------------------------------------------
// helpers
// ---------------------------------------------------------------------------
__device__ __forceinline__ unsigned sptr(const void* p) {
    return (unsigned)__cvta_generic_to_shared(p);
}
__device__ __forceinline__ void cpa16(unsigned d, const void* s) {
    asm volatile("cp.async.cg.shared.global [%0], [%1], 16;" :: "r"(d), "l"(s));
}
__device__ __forceinline__ void cp_commit() { asm volatile("cp.async.commit_group;"); }
__device__ __forceinline__ void cp_wait0()  { asm volatile("cp.async.wait_group 0;"); }
__device__ __forceinline__ void cp_wait1()  { asm volatile("cp.async.wait_group 1;"); }

__device__ __forceinline__ void ldsm4(unsigned a, unsigned* r) {
    asm volatile("ldmatrix.sync.aligned.m8n8.x4.shared.b16 {%0,%1,%2,%3},[%4];"
        : "=r"(r[0]), "=r"(r[1]), "=r"(r[2]), "=r"(r[3]) : "r"(a));
}
__device__ __forceinline__ void ldsm4t(unsigned a, unsigned* r) {
    asm volatile("ldmatrix.sync.aligned.m8n8.x4.trans.shared.b16 {%0,%1,%2,%3},[%4];"
        : "=r"(r[0]), "=r"(r[1]), "=r"(r[2]), "=r"(r[3]) : "r"(a));
}
__device__ __forceinline__ void mma_f16(float* c, const unsigned* a, unsigned b0, unsigned b1) {
    asm volatile(
        "mma.sync.aligned.m16n8k16.row.col.f32.f16.f16.f32 "
        "{%0,%1,%2,%3},{%4,%5,%6,%7},{%8,%9},{%0,%1,%2,%3};"
        : "+f"(c[0]), "+f"(c[1]), "+f"(c[2]), "+f"(c[3])
        : "r"(a[0]), "r"(a[1]), "r"(a[2]), "r"(a[3]), "r"(b0), "r"(b1));
}
__device__ __forceinline__ unsigned packh2(float v0, float v1) {
    unsigned r;
    asm("cvt.rn.f16x2.f32 %0, %1, %2;" : "=r"(r) : "f"(v1), "f"(v0));
    return r;
}

// ---------------------------------------------------------------------------
// One-time convert: x + 4 weight matrices -> fp16
// ---------------------------------------------------------------------------
__global__ void cvt_all(const float* __restrict__ x,
                        const float* __restrict__ wq, const float* __restrict__ wk,
                        const float* __restrict__ wv, const float* __restrict__ wo,
                        __half* __restrict__ X, __half* __restrict__ W)
{
    int i = blockIdx.x * blockDim.x + threadIdx.x;
    const int NX = CHUNK / 4;
    const int NW = (DIMc * DIMc) / 4;
    const float* src; __half* dst; int idx;
    if (i < NX) { src = x; dst = X; idx = i; }
    else {
        int j = i - NX;
        if (j >= 4 * NW) return;
        int m = j >> 18; idx = j & (NW - 1);
        src = (m == 0) ? wq : (m == 1) ? wk : (m == 2) ? wv : wo;
        dst = W + (size_t)m * DIMc * DIMc;
    }
    float4 v = reinterpret_cast<const float4*>(src)[idx];
    reinterpret_cast<uint2*>(dst)[idx] = make_uint2(packh2(v.x, v.y), packh2(v.z, v.w));
}

// ---------------------------------------------------------------------------
// Projection GEMM (fp16): BM=BN=128, BK=64, 3-stage cp.async, 256 thr, 2/SM.
// MODE 1: z-fused QKV (z<2 -> rope), fp16 out. MODE 0: fp32 out.
// ---------------------------------------------------------------------------
#define SPp   72            // smem row stride (halfs): 144B, LDSM conflict-free
#define PBUFp (128*SPp)     // 9216 halfs per matrix buffer

template<int MODE>
__global__ __launch_bounds__(256, 2) void proj_mma(
    const __half* __restrict__ A_g, const __half* __restrict__ WBase,
    float* __restrict__ OutF, __half* __restrict__ OBase,
    const float* __restrict__ fc, const float* __restrict__ fs)
{
    extern __shared__ __align__(16) __half ps[];   // 3 stages x 2 bufs x PBUFp

    const int tid = threadIdx.x;
    const int warp = tid >> 5, lane = tid & 31;
    const int g = lane >> 3, r7 = lane & 7;
    const int mBase = blockIdx.y * 128, nBase = blockIdx.x * 128;
    const int z = blockIdx.z;
    const __half* W_g = WBase + (size_t)z * DIMc * DIMc;
    const int wm = (warp & 3) * 32, wn = (warp >> 2) * 64;

    float c[2][8][4];
    #pragma unroll
    for (int i = 0; i < 2; i++)
        #pragma unroll
        for (int j = 0; j < 8; j++)
            #pragma unroll
            for (int k = 0; k < 4; k++) c[i][j][k] = 0.f;

    auto pload = [&](int slot, int t) {
        __half* base = ps + slot * 2 * PBUFp;
        int k0 = t * 64;
        #pragma unroll
        for (int i = 0; i < 4; i++) {
            int ch = tid + 256 * i;
            int r = ch >> 3, c8 = (ch & 7) * 8;
            cpa16(sptr(&base[r*SPp + c8]), &A_g[(size_t)(mBase + r) * DIMc + k0 + c8]);
            cpa16(sptr(&base[PBUFp + r*SPp + c8]), &W_g[(size_t)(nBase + r) * DIMc + k0 + c8]);
        }
    };

    pload(0, 0); cp_commit();
    pload(1, 1); cp_commit();

    for (int t = 0; t < 16; t++) {
        int cur = t % 3;
        if (t < 15) cp_wait1(); else cp_wait0();
        __syncthreads();
        if (t + 2 <= 15) { pload((t + 2) % 3, t + 2); cp_commit(); }

        __half* Ah = ps + cur * 2 * PBUFp;
        __half* Bh = Ah + PBUFp;

        #pragma unroll
        for (int kk = 0; kk < 64; kk += 16) {
            unsigned ah[2][4];
            #pragma unroll
            for (int mt = 0; mt < 2; mt++) {
                int row = wm + mt*16 + (g & 1)*8 + r7;
                int col = kk + (g >> 1)*8;
                ldsm4(sptr(&Ah[row*SPp + col]), ah[mt]);
            }
            #pragma unroll
            for (int np = 0; np < 4; np++) {
                int row = wn + np*16 + (g >> 1)*8 + r7;
                int col = kk + (g & 1)*8;
                unsigned bh[4];
                ldsm4(sptr(&Bh[row*SPp + col]), bh);
                mma_f16(c[0][np*2],   ah[0], bh[0], bh[1]);
                mma_f16(c[0][np*2+1], ah[0], bh[2], bh[3]);
                mma_f16(c[1][np*2],   ah[1], bh[0], bh[1]);
                mma_f16(c[1][np*2+1], ah[1], bh[2], bh[3]);
            }
        }
    }

    __half* O_g = (MODE == 1) ? OBase + (size_t)z * CHUNK : nullptr;
    const bool doRope = (MODE == 1) && (z < 2);

    #pragma unroll
    for (int mt = 0; mt < 2; mt++) {
        int row = mBase + wm + mt*16 + (lane >> 2);
        #pragma unroll
        for (int nt = 0; nt < 8; nt++) {
            int col = nBase + wn + nt*8 + (lane & 3)*2;
            float v0 = c[mt][nt][0], v1 = c[mt][nt][1];
            float v2 = c[mt][nt][2], v3 = c[mt][nt][3];
            if (doRope) {
                int i = (col & 63) >> 1;
                int s0 = row & (Sc-1), s1 = (row + 8) & (Sc-1);
                float c0 = fc[s0*32 + i], sn0 = fs[s0*32 + i];
                float c1 = fc[s1*32 + i], sn1 = fs[s1*32 + i];
                float a0 = v0, b0 = v1, a1 = v2, b1 = v3;
                v0 = a0*c0 - b0*sn0; v1 = a0*sn0 + b0*c0;
                v2 = a1*c1 - b1*sn1; v3 = a1*sn1 + b1*c1;
            }
            if (MODE == 0) {
                *(float2*)(OutF + (size_t)row * DIMc + col)     = make_float2(v0, v1);
                *(float2*)(OutF + (size_t)(row+8) * DIMc + col) = make_float2(v2, v3);
            } else {
                *(unsigned*)&O_g[(size_t)row * DIMc + col]     = packh2(v0, v1);
                *(unsigned*)&O_g[(size_t)(row+8) * DIMc + col] = packh2(v2, v3);
            }
        }
    }
}

// ---------------------------------------------------------------------------
// Attention (fp16): 64-row q-blocks, 256 threads (8 warps), 2 CTAs/SM.
// Warp layout: m16 x n64 (4 m-groups x 2 k-slice groups).
// Pass 1: QK -> exp in regs -> C-frag->A-frag -> partial PV per k-slice;
// end-of-pass smem reduction (aliases dead V buffer).
// Pass 2: 3-stage K pipeline (stage 2 reuses dead V buffer), recompute
// scores, write normalized weights (plain float2 stores, as in R10 best).
// ---------------------------------------------------------------------------
#define SQa 72
#define QB64 (64*SQa)     // 4608 halfs (Q tile)
#define KB   (128*SQa)    // 9216 halfs (K/V tiles)

__global__ __launch_bounds__(256, 2) void attn_mma(
    float* __restrict__ attn,
    const __half* __restrict__ Q_g, const __half* __restrict__ K_g,
    const __half* __restrict__ V_g, __half* __restrict__ C_g)
{
    extern __shared__ __align__(16) __half sm[];
    __half* Qh = sm;                 // QB64
    __half* Kst = Qh + QB64;         // pass1: 2 stages; pass2: 3 stages
    __half* Vh = Kst + 2*KB;         // KB (== Kst stage 2 in pass 2)
    float* rowsum = (float*)(Vh + KB);      // 64 floats
    float* red = (float*)Vh;                // 64x65 fp32, aliases dead V buffer

    const int tid = threadIdx.x;
    const int warp = tid >> 5, lane = tid & 31;
    const int g = lane >> 3, r7 = lane & 7;
    const int qBase = blockIdx.x * 64;
    const int h = blockIdx.y, b = blockIdx.z;

    const size_t qOff = (size_t)(b * Sc + qBase) * DIMc + h * HDc;
    const size_t kvOff = (size_t)b * Sc * DIMc + h * HDc;
    float* arow = attn + ((size_t)(b * NHc + h) * Sc + qBase) * Sc;

    if (tid < 64) rowsum[tid] = 0.f;

    auto kload = [&](int s, int kt) {
        __half* KH = Kst + s * KB;
        #pragma unroll
        for (int i = 0; i < 4; i++) {
            int ch = tid + 256 * i;
            int r = ch >> 3, c8 = (ch & 7) * 8;
            cpa16(sptr(&KH[r*SQa + c8]), &K_g[kvOff + (size_t)(kt + r) * DIMc + c8]);
        }
    };
    auto vload = [&](int kt) {
        #pragma unroll
        for (int i = 0; i < 4; i++) {
            int ch = tid + 256 * i;
            int r = ch >> 3, c8 = (ch & 7) * 8;
            cpa16(sptr(&Vh[r*SQa + c8]), &V_g[kvOff + (size_t)(kt + r) * DIMc + c8]);
        }
    };

    #pragma unroll
    for (int i = 0; i < 2; i++) {
        int ch = tid + 256 * i;
        int r = ch >> 3, c8 = (ch & 7) * 8;
        cpa16(sptr(&Qh[r*SQa + c8]), &Q_g[qOff + (size_t)r * DIMc + c8]);
    }
    kload(0, 0);
    cp_commit();

    const int wm = (warp & 3) * 16;     // m offset (16 rows per warp)
    const int wk = (warp >> 2) * 64;    // key-slice offset (64 keys per warp)

    float ctx[8][4];
    #pragma unroll
    for (int i = 0; i < 8; i++)
        #pragma unroll
        for (int j = 0; j < 4; j++) ctx[i][j] = 0.f;
    float rs0 = 0.f, rs1 = 0.f;

    // ---------------- pass 1 ----------------
    for (int t = 0; t < Sc / 128; t++) {
        const int cur = t & 1;
        cp_wait0();
        __syncthreads();                 // K_t visible; V slot free
        vload(t * 128); cp_commit();
        const bool pre = (t + 1 < Sc / 128);
        if (pre) { kload(cur ^ 1, (t + 1) * 128); cp_commit(); }

        __half* KH = Kst + cur * KB;

        float s[8][4];
        #pragma unroll
        for (int i = 0; i < 8; i++)
            #pragma unroll
            for (int j = 0; j < 4; j++) s[i][j] = 0.f;
        #pragma unroll
        for (int kk = 0; kk < 64; kk += 16) {
            unsigned ah[4];
            ldsm4(sptr(Qh + (wm + (g & 1)*8 + r7)*SQa + kk + (g >> 1)*8), ah);
            #pragma unroll
            for (int np = 0; np < 4; np++) {
                unsigned bh[4];
                ldsm4(sptr(KH + (wk + np*16 + (g >> 1)*8 + r7)*SQa + kk + (g & 1)*8), bh);
                mma_f16(s[np*2],   ah, bh[0], bh[1]);
                mma_f16(s[np*2+1], ah, bh[2], bh[3]);
            }
        }

        if (pre) cp_wait1(); else cp_wait0();   // V_t arrived
        __syncthreads();

        #pragma unroll
        for (int nt = 0; nt < 8; nt++) {
            s[nt][0] = __expf(s[nt][0] * 0.125f);
            s[nt][1] = __expf(s[nt][1] * 0.125f);
            s[nt][2] = __expf(s[nt][2] * 0.125f);
            s[nt][3] = __expf(s[nt][3] * 0.125f);
            rs0 += s[nt][0] + s[nt][1];
            rs1 += s[nt][2] + s[nt][3];
        }

        #pragma unroll
        for (int kc = 0; kc < 4; kc++) {
            unsigned a[4];
            a[0] = packh2(s[kc*2][0],   s[kc*2][1]);
            a[1] = packh2(s[kc*2][2],   s[kc*2][3]);
            a[2] = packh2(s[kc*2+1][0], s[kc*2+1][1]);
            a[3] = packh2(s[kc*2+1][2], s[kc*2+1][3]);
            int vrow = wk + kc*16 + (g & 1)*8 + r7;
            #pragma unroll
            for (int dp = 0; dp < 4; dp++) {
                unsigned bh[4];
                ldsm4t(sptr(Vh + vrow*SQa + dp*16 + (g >> 1)*8), bh);
                mma_f16(ctx[dp*2],   a, bh[0], bh[1]);
                mma_f16(ctx[dp*2+1], a, bh[2], bh[3]);
            }
        }
    }

    atomicAdd(&rowsum[wm + (lane >> 2)],     rs0);
    atomicAdd(&rowsum[wm + 8 + (lane >> 2)], rs1);
    __syncthreads();                      // PV done (Vh dead), atomics visible

    if (tid < 64) rowsum[tid] = 1.0f / rowsum[tid];
    if (warp < 4) {
        int r0 = wm + (lane >> 2);
        #pragma unroll
        for (int dt = 0; dt < 8; dt++) {
            int cc = dt*8 + (lane & 3)*2;
            red[r0*65 + cc]       = ctx[dt][0];
            red[r0*65 + cc + 1]   = ctx[dt][1];
            red[(r0+8)*65 + cc]   = ctx[dt][2];
            red[(r0+8)*65 + cc+1] = ctx[dt][3];
        }
    }
    __syncthreads();
    if (warp >= 4) {
        int r0 = wm + (lane >> 2);
        #pragma unroll
        for (int dt = 0; dt < 8; dt++) {
            int cc = dt*8 + (lane & 3)*2;
            red[r0*65 + cc]       += ctx[dt][0];
            red[r0*65 + cc + 1]   += ctx[dt][1];
            red[(r0+8)*65 + cc]   += ctx[dt][2];
            red[(r0+8)*65 + cc+1] += ctx[dt][3];
        }
    }
    __syncthreads();

    // prefetch pass-2 K_0, K_1 into stages 0,1 (NOT the red region) while
    // storing ctx
    kload(0, 0); cp_commit();
    kload(1, 128); cp_commit();

    #pragma unroll
    for (int i = 0; i < 8; i++) {
        int p = tid + 256 * i;
        int row = p >> 5;
        int cc = (p & 31) * 2;
        float iv = rowsum[row];
        *(unsigned*)&C_g[qOff + (size_t)row * DIMc + cc] =
            packh2(red[row*65 + cc] * iv, red[row*65 + cc + 1] * iv);
    }

    const float iv0 = rowsum[wm + (lane >> 2)];
    const float iv1 = rowsum[wm + 8 + (lane >> 2)];
    __syncthreads();   // all red/rowsum reads done before stage-2 kload hits it

    // ---------------- pass 2: 3-stage pipeline, recompute, write ----------
    for (int t = 0; t < Sc / 128; t++) {
        const int cur = t % 3;
        const int kt = t * 128;
        if (t < Sc/128 - 1) cp_wait1(); else cp_wait0();   // K_t ready
        __syncthreads();
        if (t + 2 <= Sc/128 - 1) { kload((t + 2) % 3, kt + 256); cp_commit(); }

        __half* KH = Kst + cur * KB;

        float s[8][4];
        #pragma unroll
        for (int i = 0; i < 8; i++)
            #pragma unroll
            for (int j = 0; j < 4; j++) s[i][j] = 0.f;
        #pragma unroll
        for (int kk = 0; kk < 64; kk += 16) {
            unsigned ah[4];
            ldsm4(sptr(Qh + (wm + (g & 1)*8 + r7)*SQa + kk + (g >> 1)*8), ah);
            #pragma unroll
            for (int np = 0; np < 4; np++) {
                unsigned bh[4];
                ldsm4(sptr(KH + (wk + np*16 + (g >> 1)*8 + r7)*SQa + kk + (g & 1)*8), bh);
                mma_f16(s[np*2],   ah, bh[0], bh[1]);
                mma_f16(s[np*2+1], ah, bh[2], bh[3]);
            }
        }

        int row0 = wm + (lane >> 2);
        #pragma unroll
        for (int nt = 0; nt < 8; nt++) {
            int col = wk + nt*8 + (lane & 3)*2;
            float e0 = __expf(s[nt][0] * 0.125f) * iv0;
            float e1 = __expf(s[nt][1] * 0.125f) * iv0;
            float e2 = __expf(s[nt][2] * 0.125f) * iv1;
            float e3 = __expf(s[nt][3] * 0.125f) * iv1;
            *(float2*)(arow + (size_t)row0 * Sc + kt + col)     = make_float2(e0, e1);
            *(float2*)(arow + (size_t)(row0+8) * Sc + kt + col) = make_float2(e2, e3);
        }
    }
}

// ---------------------------------------------------------------------------
// Launcher
// ---------------------------------------------------------------------------
extern "C" void kernel_launch(void* const* d_in, const int* in_sizes, int n_in,
                              void* d_out, int out_size)
{
    const float* x  = (const float*)d_in[0];
    const float* wq = (const float*)d_in[1];
    const float* wk = (const float*)d_in[2];
    const float* wv = (const float*)d_in[3];
    const float* wo = (const float*)d_in[4];
    const float* fc = (const float*)d_in[5];
    const float* fs = (const float*)d_in[6];

    float* out  = (float*)d_out;
    float* attn = out + (size_t)Bc * Sc * DIMc;

    __half* buf;
    cudaGetSymbolAddress((void**)&buf, g_buf);
    const size_t WM = (size_t)DIMc * DIMc;
    __half* X = buf;
    __half* W = buf + 1ull*CHUNK;
    __half* Q = buf + 2ull*CHUNK;    // Q,K,V contiguous (z-indexed)
    __half* C = buf + 5ull*CHUNK;

    const int projSmem = 3 * 2 * PBUFp * 2;                 // 110,592 B
    cudaFuncSetAttribute(proj_mma<0>, cudaFuncAttributeMaxDynamicSharedMemorySize, projSmem);
    cudaFuncSetAttribute(proj_mma<1>, cudaFuncAttributeMaxDynamicSharedMemorySize, projSmem);
    const int attnSmem = (QB64 + 3*KB) * 2 + 64 * 4;        // 64,768 B
    cudaFuncSetAttribute(attn_mma, cudaFuncAttributeMaxDynamicSharedMemorySize, attnSmem);

    int nCvt = CHUNK / 4 + DIMc * DIMc;
    cvt_all<<<(nCvt + 255) / 256, 256>>>(x, wq, wk, wv, wo, X, W);

    // fused QKV (z=0 Q rope, z=1 K rope, z=2 V)
    proj_mma<1><<<dim3(DIMc/128, TTOT/128, 3), 256, projSmem>>>(X, W, nullptr, Q, fc, fs);

    attn_mma<<<dim3(Sc/64, NHc, Bc), 256, attnSmem>>>(attn, Q, Q + 1ull*CHUNK, Q + 2ull*CHUNK, C);

    proj_mma<0><<<dim3(DIMc/128, TTOT/128, 1), 256, projSmem>>>(C, W + 3*WM, out, nullptr, nullptr, nullptr);
}

// round 16
// speedup vs baseline: 1.0938x; 1.0122x over previous
#include <cuda_runtime.h>
#include <cuda_fp16.h>
#include <cstdint>

#define Bc   2
#define Sc   2048
#define DIMc 1024
#define NHc  16
#define HDc  64
#define TTOT (Bc*Sc)
#define CHUNK (TTOT*DIMc)          // 4,194,304 elements

// Scratch arena (fp16), CHUNK units: 0 X | 1 W(4 mats) | 2 Q | 3 K | 4 V | 5 C
__device__ __half g_buf[6ull * CHUNK];

// ---------------------------------------------------------------------------
// helpers
// ---------------------------------------------------------------------------
__device__ __forceinline__ unsigned sptr(const void* p) {
    return (unsigned)__cvta_generic_to_shared(p);
}
__device__ __forceinline__ void cpa16(unsigned d, const void* s) {
    asm volatile("cp.async.cg.shared.global [%0], [%1], 16;" :: "r"(d), "l"(s));
}
__device__ __forceinline__ void cp_commit() { asm volatile("cp.async.commit_group;"); }
__device__ __forceinline__ void cp_wait0()  { asm volatile("cp.async.wait_group 0;"); }
__device__ __forceinline__ void cp_wait1()  { asm volatile("cp.async.wait_group 1;"); }

__device__ __forceinline__ void ldsm4(unsigned a, unsigned* r) {
    asm volatile("ldmatrix.sync.aligned.m8n8.x4.shared.b16 {%0,%1,%2,%3},[%4];"
        : "=r"(r[0]), "=r"(r[1]), "=r"(r[2]), "=r"(r[3]) : "r"(a));
}
__device__ __forceinline__ void ldsm4t(unsigned a, unsigned* r) {
    asm volatile("ldmatrix.sync.aligned.m8n8.x4.trans.shared.b16 {%0,%1,%2,%3},[%4];"
        : "=r"(r[0]), "=r"(r[1]), "=r"(r[2]), "=r"(r[3]) : "r"(a));
}
__device__ __forceinline__ void mma_f16(float* c, const unsigned* a, unsigned b0, unsigned b1) {
    asm volatile(
        "mma.sync.aligned.m16n8k16.row.col.f32.f16.f16.f32 "
        "{%0,%1,%2,%3},{%4,%5,%6,%7},{%8,%9},{%0,%1,%2,%3};"
        : "+f"(c[0]), "+f"(c[1]), "+f"(c[2]), "+f"(c[3])
        : "r"(a[0]), "r"(a[1]), "r"(a[2]), "r"(a[3]), "r"(b0), "r"(b1));
}
__device__ __forceinline__ unsigned packh2(float v0, float v1) {
    unsigned r;
    asm("cvt.rn.f16x2.f32 %0, %1, %2;" : "=r"(r) : "f"(v1), "f"(v0));
    return r;
}

// ---------------------------------------------------------------------------
// One-time convert: x + 4 weight matrices -> fp16 (2 float4s per thread, ILP)
// ---------------------------------------------------------------------------
__global__ void cvt_all(const float* __restrict__ x,
                        const float* __restrict__ wq, const float* __restrict__ wk,
                        const float* __restrict__ wv, const float* __restrict__ wo,
                        __half* __restrict__ X, __half* __restrict__ W)
{
    const int NX = CHUNK / 4;                 // 1,048,576 float4s in x
    const int NW = (DIMc * DIMc) / 4;         // 262,144 per weight
    int base = blockIdx.x * blockDim.x * 2 + threadIdx.x;

    #pragma unroll
    for (int u = 0; u < 2; u++) {
        int i = base + u * blockDim.x;
        const float* src; __half* dst; int idx;
        if (i < NX) { src = x; dst = X; idx = i; }
        else {
            int j = i - NX;
            if (j >= 4 * NW) continue;
            int m = j >> 18; idx = j & (NW - 1);
            src = (m == 0) ? wq : (m == 1) ? wk : (m == 2) ? wv : wo;
            dst = W + (size_t)m * DIMc * DIMc;
        }
        float4 v = reinterpret_cast<const float4*>(src)[idx];
        reinterpret_cast<uint2*>(dst)[idx] = make_uint2(packh2(v.x, v.y), packh2(v.z, v.w));
    }
}

// ---------------------------------------------------------------------------
// Projection GEMM (fp16): BM=BN=128, BK=64, 3-stage cp.async, 256 thr, 2/SM.
// MODE 1: z-fused QKV (z<2 -> rope), fp16 out. MODE 0: fp32 out.
// ---------------------------------------------------------------------------
#define SPp   72            // smem row stride (halfs): 144B, LDSM conflict-free
#define PBUFp (128*SPp)     // 9216 halfs per matrix buffer

template<int MODE>
__global__ __launch_bounds__(256, 2) void proj_mma(
    const __half* __restrict__ A_g, const __half* __restrict__ WBase,
    float* __restrict__ OutF, __half* __restrict__ OBase,
    const float* __restrict__ fc, const float* __restrict__ fs)
{
    extern __shared__ __align__(16) __half ps[];   // 3 stages x 2 bufs x PBUFp

    const int tid = threadIdx.x;
    const int warp = tid >> 5, lane = tid & 31;
    const int g = lane >> 3, r7 = lane & 7;
    const int mBase = blockIdx.y * 128, nBase = blockIdx.x * 128;
    const int z = blockIdx.z;
    const __half* W_g = WBase + (size_t)z * DIMc * DIMc;
    const int wm = (warp & 3) * 32, wn = (warp >> 2) * 64;

    float c[2][8][4];
    #pragma unroll
    for (int i = 0; i < 2; i++)
        #pragma unroll
        for (int j = 0; j < 8; j++)
            #pragma unroll
            for (int k = 0; k < 4; k++) c[i][j][k] = 0.f;

    auto pload = [&](int slot, int t) {
        __half* base = ps + slot * 2 * PBUFp;
        int k0 = t * 64;
        #pragma unroll
        for (int i = 0; i < 4; i++) {
            int ch = tid + 256 * i;
            int r = ch >> 3, c8 = (ch & 7) * 8;
            cpa16(sptr(&base[r*SPp + c8]), &A_g[(size_t)(mBase + r) * DIMc + k0 + c8]);
            cpa16(sptr(&base[PBUFp + r*SPp + c8]), &W_g[(size_t)(nBase + r) * DIMc + k0 + c8]);
        }
    };

    pload(0, 0); cp_commit();
    pload(1, 1); cp_commit();

    for (int t = 0; t < 16; t++) {
        int cur = t % 3;
        if (t < 15) cp_wait1(); else cp_wait0();
        __syncthreads();
        if (t + 2 <= 15) { pload((t + 2) % 3, t + 2); cp_commit(); }

        __half* Ah = ps + cur * 2 * PBUFp;
        __half* Bh = Ah + PBUFp;

        #pragma unroll
        for (int kk = 0; kk < 64; kk += 16) {
            unsigned ah[2][4];
            #pragma unroll
            for (int mt = 0; mt < 2; mt++) {
                int row = wm + mt*16 + (g & 1)*8 + r7;
                int col = kk + (g >> 1)*8;
                ldsm4(sptr(&Ah[row*SPp + col]), ah[mt]);
            }
            #pragma unroll
            for (int np = 0; np < 4; np++) {
                int row = wn + np*16 + (g >> 1)*8 + r7;
                int col = kk + (g & 1)*8;
                unsigned bh[4];
                ldsm4(sptr(&Bh[row*SPp + col]), bh);
                mma_f16(c[0][np*2],   ah[0], bh[0], bh[1]);
                mma_f16(c[0][np*2+1], ah[0], bh[2], bh[3]);
                mma_f16(c[1][np*2],   ah[1], bh[0], bh[1]);
                mma_f16(c[1][np*2+1], ah[1], bh[2], bh[3]);
            }
        }
    }

    __half* O_g = (MODE == 1) ? OBase + (size_t)z * CHUNK : nullptr;
    const bool doRope = (MODE == 1) && (z < 2);

    #pragma unroll
    for (int mt = 0; mt < 2; mt++) {
        int row = mBase + wm + mt*16 + (lane >> 2);
        #pragma unroll
        for (int nt = 0; nt < 8; nt++) {
            int col = nBase + wn + nt*8 + (lane & 3)*2;
            float v0 = c[mt][nt][0], v1 = c[mt][nt][1];
            float v2 = c[mt][nt][2], v3 = c[mt][nt][3];
            if (doRope) {
                int i = (col & 63) >> 1;
                int s0 = row & (Sc-1), s1 = (row + 8) & (Sc-1);
                float c0 = fc[s0*32 + i], sn0 = fs[s0*32 + i];
                float c1 = fc[s1*32 + i], sn1 = fs[s1*32 + i];
                float a0 = v0, b0 = v1, a1 = v2, b1 = v3;
                v0 = a0*c0 - b0*sn0; v1 = a0*sn0 + b0*c0;
                v2 = a1*c1 - b1*sn1; v3 = a1*sn1 + b1*c1;
            }
            if (MODE == 0) {
                *(float2*)(OutF + (size_t)row * DIMc + col)     = make_float2(v0, v1);
                *(float2*)(OutF + (size_t)(row+8) * DIMc + col) = make_float2(v2, v3);
            } else {
                *(unsigned*)&O_g[(size_t)row * DIMc + col]     = packh2(v0, v1);
                *(unsigned*)&O_g[(size_t)(row+8) * DIMc + col] = packh2(v2, v3);
            }
        }
    }
}

// ---------------------------------------------------------------------------
// Attention (fp16): 64-row q-blocks, 256 threads (8 warps), 2 CTAs/SM.
// Warp layout: m16 x n64 (4 m-groups x 2 k-slice groups).
// Pass 1: QK -> exp in regs -> C-frag->A-frag -> partial PV per k-slice;
// end-of-pass smem reduction (aliases dead V buffer).
// Pass 2: recompute scores, write normalized weights. (R10 configuration.)
// ---------------------------------------------------------------------------
#define SQa 72
#define QB64 (64*SQa)     // 4608 halfs (Q tile)
#define KB   (128*SQa)    // 9216 halfs (K/V tiles)

__global__ __launch_bounds__(256, 2) void attn_mma(
    float* __restrict__ attn,
    const __half* __restrict__ Q_g, const __half* __restrict__ K_g,
    const __half* __restrict__ V_g, __half* __restrict__ C_g)
{
    extern __shared__ __align__(16) __half sm[];
    __half* Qh = sm;                 // QB64
    __half* Kst = Qh + QB64;         // 2 stages x KB
    __half* Vh = Kst + 2*KB;         // KB
    float* rowsum = (float*)(Vh + KB);      // 64 floats
    float* red = (float*)Vh;                // 64x65 fp32, aliases dead V buffer

    const int tid = threadIdx.x;
    const int warp = tid >> 5, lane = tid & 31;
    const int g = lane >> 3, r7 = lane & 7;
    const int qBase = blockIdx.x * 64;
    const int h = blockIdx.y, b = blockIdx.z;

    const size_t qOff = (size_t)(b * Sc + qBase) * DIMc + h * HDc;
    const size_t kvOff = (size_t)b * Sc * DIMc + h * HDc;
    float* arow = attn + ((size_t)(b * NHc + h) * Sc + qBase) * Sc;

    if (tid < 64) rowsum[tid] = 0.f;

    auto kload = [&](int s, int kt) {
        __half* KH = Kst + s * KB;
        #pragma unroll
        for (int i = 0; i < 4; i++) {
            int ch = tid + 256 * i;
            int r = ch >> 3, c8 = (ch & 7) * 8;
            cpa16(sptr(&KH[r*SQa + c8]), &K_g[kvOff + (size_t)(kt + r) * DIMc + c8]);
        }
    };
    auto vload = [&](int kt) {
        #pragma unroll
        for (int i = 0; i < 4; i++) {
            int ch = tid + 256 * i;
            int r = ch >> 3, c8 = (ch & 7) * 8;
            cpa16(sptr(&Vh[r*SQa + c8]), &V_g[kvOff + (size_t)(kt + r) * DIMc + c8]);
        }
    };

    #pragma unroll
    for (int i = 0; i < 2; i++) {
        int ch = tid + 256 * i;
        int r = ch >> 3, c8 = (ch & 7) * 8;
        cpa16(sptr(&Qh[r*SQa + c8]), &Q_g[qOff + (size_t)r * DIMc + c8]);
    }
    kload(0, 0);
    cp_commit();

    const int wm = (warp & 3) * 16;     // m offset (16 rows per warp)
    const int wk = (warp >> 2) * 64;    // key-slice offset (64 keys per warp)

    float ctx[8][4];
    #pragma unroll
    for (int i = 0; i < 8; i++)
        #pragma unroll
        for (int j = 0; j < 4; j++) ctx[i][j] = 0.f;
    float rs0 = 0.f, rs1 = 0.f;

    // ---------------- pass 1 ----------------
    for (int t = 0; t < Sc / 128; t++) {
        const int cur = t & 1;
        cp_wait0();
        __syncthreads();                 // K_t visible; V slot free
        vload(t * 128); cp_commit();
        const bool pre = (t + 1 < Sc / 128);
        if (pre) { kload(cur ^ 1, (t + 1) * 128); cp_commit(); }

        __half* KH = Kst + cur * KB;

        float s[8][4];
        #pragma unroll
        for (int i = 0; i < 8; i++)
            #pragma unroll
            for (int j = 0; j < 4; j++) s[i][j] = 0.f;
        #pragma unroll
        for (int kk = 0; kk < 64; kk += 16) {
            unsigned ah[4];
            ldsm4(sptr(Qh + (wm + (g & 1)*8 + r7)*SQa + kk + (g >> 1)*8), ah);
            #pragma unroll
            for (int np = 0; np < 4; np++) {
                unsigned bh[4];
                ldsm4(sptr(KH + (wk + np*16 + (g >> 1)*8 + r7)*SQa + kk + (g & 1)*8), bh);
                mma_f16(s[np*2],   ah, bh[0], bh[1]);
                mma_f16(s[np*2+1], ah, bh[2], bh[3]);
            }
        }

        if (pre) cp_wait1(); else cp_wait0();   // V_t arrived
        __syncthreads();

        #pragma unroll
        for (int nt = 0; nt < 8; nt++) {
            s[nt][0] = __expf(s[nt][0] * 0.125f);
            s[nt][1] = __expf(s[nt][1] * 0.125f);
            s[nt][2] = __expf(s[nt][2] * 0.125f);
            s[nt][3] = __expf(s[nt][3] * 0.125f);
            rs0 += s[nt][0] + s[nt][1];
            rs1 += s[nt][2] + s[nt][3];
        }

        #pragma unroll
        for (int kc = 0; kc < 4; kc++) {
            unsigned a[4];
            a[0] = packh2(s[kc*2][0],   s[kc*2][1]);
            a[1] = packh2(s[kc*2][2],   s[kc*2][3]);
            a[2] = packh2(s[kc*2+1][0], s[kc*2+1][1]);
            a[3] = packh2(s[kc*2+1][2], s[kc*2+1][3]);
            int vrow = wk + kc*16 + (g & 1)*8 + r7;
            #pragma unroll
            for (int dp = 0; dp < 4; dp++) {
                unsigned bh[4];
                ldsm4t(sptr(Vh + vrow*SQa + dp*16 + (g >> 1)*8), bh);
                mma_f16(ctx[dp*2],   a, bh[0], bh[1]);
                mma_f16(ctx[dp*2+1], a, bh[2], bh[3]);
            }
        }
    }

    atomicAdd(&rowsum[wm + (lane >> 2)],     rs0);
    atomicAdd(&rowsum[wm + 8 + (lane >> 2)], rs1);
    __syncthreads();                      // PV done (Vh dead), atomics visible

    if (tid < 64) rowsum[tid] = 1.0f / rowsum[tid];
    if (warp < 4) {
        int r0 = wm + (lane >> 2);
        #pragma unroll
        for (int dt = 0; dt < 8; dt++) {
            int cc = dt*8 + (lane & 3)*2;
            red[r0*65 + cc]       = ctx[dt][0];
            red[r0*65 + cc + 1]   = ctx[dt][1];
            red[(r0+8)*65 + cc]   = ctx[dt][2];
            red[(r0+8)*65 + cc+1] = ctx[dt][3];
        }
    }
    __syncthreads();
    if (warp >= 4) {
        int r0 = wm + (lane >> 2);
        #pragma unroll
        for (int dt = 0; dt < 8; dt++) {
            int cc = dt*8 + (lane & 3)*2;
            red[r0*65 + cc]       += ctx[dt][0];
            red[r0*65 + cc + 1]   += ctx[dt][1];
            red[(r0+8)*65 + cc]   += ctx[dt][2];
            red[(r0+8)*65 + cc+1] += ctx[dt][3];
        }
    }
    __syncthreads();

    // prefetch pass-2 K_0 while we store ctx
    kload(0, 0); cp_commit();

    #pragma unroll
    for (int i = 0; i < 8; i++) {
        int p = tid + 256 * i;
        int row = p >> 5;
        int cc = (p & 31) * 2;
        float iv = rowsum[row];
        *(unsigned*)&C_g[qOff + (size_t)row * DIMc + cc] =
            packh2(red[row*65 + cc] * iv, red[row*65 + cc + 1] * iv);
    }

    const float iv0 = rowsum[wm + (lane >> 2)];
    const float iv1 = rowsum[wm + 8 + (lane >> 2)];
    __syncthreads();

    // ---------------- pass 2: recompute scores, write normalized ----------
    for (int t = 0; t < Sc / 128; t++) {
        const int cur = t & 1;
        const int kt = t * 128;
        cp_wait0();
        __syncthreads();
        if (t + 1 < Sc / 128) { kload(cur ^ 1, kt + 128); cp_commit(); }

        __half* KH = Kst + cur * KB;

        float s[8][4];
        #pragma unroll
        for (int i = 0; i < 8; i++)
            #pragma unroll
            for (int j = 0; j < 4; j++) s[i][j] = 0.f;
        #pragma unroll
        for (int kk = 0; kk < 64; kk += 16) {
            unsigned ah[4];
            ldsm4(sptr(Qh + (wm + (g & 1)*8 + r7)*SQa + kk + (g >> 1)*8), ah);
            #pragma unroll
            for (int np = 0; np < 4; np++) {
                unsigned bh[4];
                ldsm4(sptr(KH + (wk + np*16 + (g >> 1)*8 + r7)*SQa + kk + (g & 1)*8), bh);
                mma_f16(s[np*2],   ah, bh[0], bh[1]);
                mma_f16(s[np*2+1], ah, bh[2], bh[3]);
            }
        }

        int row0 = wm + (lane >> 2);
        #pragma unroll
        for (int nt = 0; nt < 8; nt++) {
            int col = wk + nt*8 + (lane & 3)*2;
            float e0 = __expf(s[nt][0] * 0.125f) * iv0;
            float e1 = __expf(s[nt][1] * 0.125f) * iv0;
            float e2 = __expf(s[nt][2] * 0.125f) * iv1;
            float e3 = __expf(s[nt][3] * 0.125f) * iv1;
            *(float2*)(arow + (size_t)row0 * Sc + kt + col)     = make_float2(e0, e1);
            *(float2*)(arow + (size_t)(row0+8) * Sc + kt + col) = make_float2(e2, e3);
        }
    }
}

// ---------------------------------------------------------------------------
// Launcher
// ---------------------------------------------------------------------------
extern "C" void kernel_launch(void* const* d_in, const int* in_sizes, int n_in,
                              void* d_out, int out_size)
{
    const float* x  = (const float*)d_in[0];
    const float* wq = (const float*)d_in[1];
    const float* wk = (const float*)d_in[2];
    const float* wv = (const float*)d_in[3];
    const float* wo = (const float*)d_in[4];
    const float* fc = (const float*)d_in[5];
    const float* fs = (const float*)d_in[6];

    float* out  = (float*)d_out;
    float* attn = out + (size_t)Bc * Sc * DIMc;

    __half* buf;
    cudaGetSymbolAddress((void**)&buf, g_buf);
    const size_t WM = (size_t)DIMc * DIMc;
    __half* X = buf;
    __half* W = buf + 1ull*CHUNK;
    __half* Q = buf + 2ull*CHUNK;    // Q,K,V contiguous (z-indexed)
    __half* C = buf + 5ull*CHUNK;

    const int projSmem = 3 * 2 * PBUFp * 2;                 // 110,592 B
    cudaFuncSetAttribute(proj_mma<0>, cudaFuncAttributeMaxDynamicSharedMemorySize, projSmem);
    cudaFuncSetAttribute(proj_mma<1>, cudaFuncAttributeMaxDynamicSharedMemorySize, projSmem);
    const int attnSmem = (QB64 + 3*KB) * 2 + 64 * 4;        // 64,768 B
    cudaFuncSetAttribute(attn_mma, cudaFuncAttributeMaxDynamicSharedMemorySize, attnSmem);

    int nCvt = CHUNK / 4 + DIMc * DIMc;    // total float4s
    cvt_all<<<(nCvt + 511) / 512, 256>>>(x, wq, wk, wv, wo, X, W);

    // fused QKV (z=0 Q rope, z=1 K rope, z=2 V)
    proj_mma<1><<<dim3(DIMc/128, TTOT/128, 3), 256, projSmem>>>(X, W, nullptr, Q, fc, fs);

    attn_mma<<<dim3(Sc/64, NHc, Bc), 256, attnSmem>>>(attn, Q, Q + 1ull*CHUNK, Q + 2ull*CHUNK, C);

    proj_mma<0><<<dim3(DIMc/128, TTOT/128, 1), 256, projSmem>>>(C, W + 3*WM, out, nullptr, nullptr, nullptr);
}

// round 17
// speedup vs baseline: 1.1080x; 1.0130x over previous
#include <cuda_runtime.h>
#include <cuda_fp16.h>
#include <cstdint>

#define Bc   2
#define Sc   2048
#define DIMc 1024
#define NHc  16
#define HDc  64
#define TTOT (Bc*Sc)
#define CHUNK (TTOT*DIMc)          // 4,194,304 elements

// Scratch arena (fp16), CHUNK units: 0 X | 1 W(4 mats) | 2 Q | 3 K | 4 V | 5 C
__device__ __half g_buf[6ull * CHUNK];

// ---------------------------------------------------------------------------
// helpers
// ---------------------------------------------------------------------------
__device__ __forceinline__ unsigned sptr(const void* p) {
    return (unsigned)__cvta_generic_to_shared(p);
}
__device__ __forceinline__ void cpa16(unsigned d, const void* s) {
    asm volatile("cp.async.cg.shared.global [%0], [%1], 16;" :: "r"(d), "l"(s));
}
__device__ __forceinline__ void cp_commit() { asm volatile("cp.async.commit_group;"); }
__device__ __forceinline__ void cp_wait0()  { asm volatile("cp.async.wait_group 0;"); }
__device__ __forceinline__ void cp_wait1()  { asm volatile("cp.async.wait_group 1;"); }

__device__ __forceinline__ void ldsm4(unsigned a, unsigned* r) {
    asm volatile("ldmatrix.sync.aligned.m8n8.x4.shared.b16 {%0,%1,%2,%3},[%4];"
        : "=r"(r[0]), "=r"(r[1]), "=r"(r[2]), "=r"(r[3]) : "r"(a));
}
__device__ __forceinline__ void ldsm4t(unsigned a, unsigned* r) {
    asm volatile("ldmatrix.sync.aligned.m8n8.x4.trans.shared.b16 {%0,%1,%2,%3},[%4];"
        : "=r"(r[0]), "=r"(r[1]), "=r"(r[2]), "=r"(r[3]) : "r"(a));
}
__device__ __forceinline__ void mma_f16(float* c, const unsigned* a, unsigned b0, unsigned b1) {
    asm volatile(
        "mma.sync.aligned.m16n8k16.row.col.f32.f16.f16.f32 "
        "{%0,%1,%2,%3},{%4,%5,%6,%7},{%8,%9},{%0,%1,%2,%3};"
        : "+f"(c[0]), "+f"(c[1]), "+f"(c[2]), "+f"(c[3])
        : "r"(a[0]), "r"(a[1]), "r"(a[2]), "r"(a[3]), "r"(b0), "r"(b1));
}
__device__ __forceinline__ unsigned packh2(float v0, float v1) {
    unsigned r;
    asm("cvt.rn.f16x2.f32 %0, %1, %2;" : "=r"(r) : "f"(v1), "f"(v0));
    return r;
}

// ---------------------------------------------------------------------------
// One-time convert: x + 4 weight matrices -> fp16
// ---------------------------------------------------------------------------
__global__ void cvt_all(const float* __restrict__ x,
                        const float* __restrict__ wq, const float* __restrict__ wk,
                        const float* __restrict__ wv, const float* __restrict__ wo,
                        __half* __restrict__ X, __half* __restrict__ W)
{
    int i = blockIdx.x * blockDim.x + threadIdx.x;
    const int NX = CHUNK / 4;
    const int NW = (DIMc * DIMc) / 4;
    const float* src; __half* dst; int idx;
    if (i < NX) { src = x; dst = X; idx = i; }
    else {
        int j = i - NX;
        if (j >= 4 * NW) return;
        int m = j >> 18; idx = j & (NW - 1);
        src = (m == 0) ? wq : (m == 1) ? wk : (m == 2) ? wv : wo;
        dst = W + (size_t)m * DIMc * DIMc;
    }
    float4 v = reinterpret_cast<const float4*>(src)[idx];
    reinterpret_cast<uint2*>(dst)[idx] = make_uint2(packh2(v.x, v.y), packh2(v.z, v.w));
}

// ---------------------------------------------------------------------------
// Projection GEMM (fp16): BM=BN=128, BK=64, 3-stage cp.async, 256 thr, 2/SM.
// MODE 1: z-fused QKV (z<2 -> rope), fp16 out. MODE 0: fp32 out.
// ---------------------------------------------------------------------------
#define SPp   72            // smem row stride (halfs): 144B, LDSM conflict-free
#define PBUFp (128*SPp)     // 9216 halfs per matrix buffer

template<int MODE>
__global__ __launch_bounds__(256, 2) void proj_mma(
    const __half* __restrict__ A_g, const __half* __restrict__ WBase,
    float* __restrict__ OutF, __half* __restrict__ OBase,
    const float* __restrict__ fc, const float* __restrict__ fs)
{
    extern __shared__ __align__(16) __half ps[];   // 3 stages x 2 bufs x PBUFp

    const int tid = threadIdx.x;
    const int warp = tid >> 5, lane = tid & 31;
    const int g = lane >> 3, r7 = lane & 7;
    const int mBase = blockIdx.y * 128, nBase = blockIdx.x * 128;
    const int z = blockIdx.z;
    const __half* W_g = WBase + (size_t)z * DIMc * DIMc;
    const int wm = (warp & 3) * 32, wn = (warp >> 2) * 64;

    float c[2][8][4];
    #pragma unroll
    for (int i = 0; i < 2; i++)
        #pragma unroll
        for (int j = 0; j < 8; j++)
            #pragma unroll
            for (int k = 0; k < 4; k++) c[i][j][k] = 0.f;

    auto pload = [&](int slot, int t) {
        __half* base = ps + slot * 2 * PBUFp;
        int k0 = t * 64;
        #pragma unroll
        for (int i = 0; i < 4; i++) {
            int ch = tid + 256 * i;
            int r = ch >> 3, c8 = (ch & 7) * 8;
            cpa16(sptr(&base[r*SPp + c8]), &A_g[(size_t)(mBase + r) * DIMc + k0 + c8]);
            cpa16(sptr(&base[PBUFp + r*SPp + c8]), &W_g[(size_t)(nBase + r) * DIMc + k0 + c8]);
        }
    };

    pload(0, 0); cp_commit();
    pload(1, 1); cp_commit();

    for (int t = 0; t < 16; t++) {
        int cur = t % 3;
        if (t < 15) cp_wait1(); else cp_wait0();
        __syncthreads();
        if (t + 2 <= 15) { pload((t + 2) % 3, t + 2); cp_commit(); }

        __half* Ah = ps + cur * 2 * PBUFp;
        __half* Bh = Ah + PBUFp;

        #pragma unroll
        for (int kk = 0; kk < 64; kk += 16) {
            unsigned ah[2][4];
            #pragma unroll
            for (int mt = 0; mt < 2; mt++) {
                int row = wm + mt*16 + (g & 1)*8 + r7;
                int col = kk + (g >> 1)*8;
                ldsm4(sptr(&Ah[row*SPp + col]), ah[mt]);
            }
            #pragma unroll
            for (int np = 0; np < 4; np++) {
                int row = wn + np*16 + (g >> 1)*8 + r7;
                int col = kk + (g & 1)*8;
                unsigned bh[4];
                ldsm4(sptr(&Bh[row*SPp + col]), bh);
                mma_f16(c[0][np*2],   ah[0], bh[0], bh[1]);
                mma_f16(c[0][np*2+1], ah[0], bh[2], bh[3]);
                mma_f16(c[1][np*2],   ah[1], bh[0], bh[1]);
                mma_f16(c[1][np*2+1], ah[1], bh[2], bh[3]);
            }
        }
    }

    __half* O_g = (MODE == 1) ? OBase + (size_t)z * CHUNK : nullptr;
    const bool doRope = (MODE == 1) && (z < 2);

    #pragma unroll
    for (int mt = 0; mt < 2; mt++) {
        int row = mBase + wm + mt*16 + (lane >> 2);
        #pragma unroll
        for (int nt = 0; nt < 8; nt++) {
            int col = nBase + wn + nt*8 + (lane & 3)*2;
            float v0 = c[mt][nt][0], v1 = c[mt][nt][1];
            float v2 = c[mt][nt][2], v3 = c[mt][nt][3];
            if (doRope) {
                int i = (col & 63) >> 1;
                int s0 = row & (Sc-1), s1 = (row + 8) & (Sc-1);
                float c0 = fc[s0*32 + i], sn0 = fs[s0*32 + i];
                float c1 = fc[s1*32 + i], sn1 = fs[s1*32 + i];
                float a0 = v0, b0 = v1, a1 = v2, b1 = v3;
                v0 = a0*c0 - b0*sn0; v1 = a0*sn0 + b0*c0;
                v2 = a1*c1 - b1*sn1; v3 = a1*sn1 + b1*c1;
            }
            if (MODE == 0) {
                *(float2*)(OutF + (size_t)row * DIMc + col)     = make_float2(v0, v1);
                *(float2*)(OutF + (size_t)(row+8) * DIMc + col) = make_float2(v2, v3);
            } else {
                *(unsigned*)&O_g[(size_t)row * DIMc + col]     = packh2(v0, v1);
                *(unsigned*)&O_g[(size_t)(row+8) * DIMc + col] = packh2(v2, v3);
            }
        }
    }
}

// ---------------------------------------------------------------------------
// Attention (fp16): 64-row q-blocks, 256 threads (8 warps), 2 CTAs/SM.
// Warp layout: m16 x n64 (warps: 4 m-groups x 2 k-slice groups).
// Pass 1: QK -> exp in regs -> C-frag->A-frag conversion -> partial PV per
// k-slice; end-of-kernel smem reduction (aliases dead V buffer).
// Pass 2: recompute scores, write normalized weights.
// ---------------------------------------------------------------------------
#define SQa 72
#define QB64 (64*SQa)     // 4608 halfs (Q tile)
#define KB   (128*SQa)    // 9216 halfs (K/V tiles)

__global__ __launch_bounds__(256, 2) void attn_mma(
    float* __restrict__ attn,
    const __half* __restrict__ Q_g, const __half* __restrict__ K_g,
    const __half* __restrict__ V_g, __half* __restrict__ C_g)
{
    extern __shared__ __align__(16) __half sm[];
    __half* Qh = sm;                 // QB64
    __half* Kst = Qh + QB64;         // 2 stages x KB
    __half* Vh = Kst + 2*KB;         // KB
    float* rowsum = (float*)(Vh + KB);      // 64 floats
    float* red = (float*)Vh;                // 64x65 fp32, aliases dead V buffer

    const int tid = threadIdx.x;
    const int warp = tid >> 5, lane = tid & 31;
    const int g = lane >> 3, r7 = lane & 7;
    const int qBase = blockIdx.x * 64;
    const int h = blockIdx.y, b = blockIdx.z;

    const size_t qOff = (size_t)(b * Sc + qBase) * DIMc + h * HDc;
    const size_t kvOff = (size_t)b * Sc * DIMc + h * HDc;
    float* arow = attn + ((size_t)(b * NHc + h) * Sc + qBase) * Sc;

    if (tid < 64) rowsum[tid] = 0.f;

    auto kload = [&](int s, int kt) {
        __half* KH = Kst + s * KB;
        #pragma unroll
        for (int i = 0; i < 4; i++) {
            int ch = tid + 256 * i;
            int r = ch >> 3, c8 = (ch & 7) * 8;
            cpa16(sptr(&KH[r*SQa + c8]), &K_g[kvOff + (size_t)(kt + r) * DIMc + c8]);
        }
    };
    auto vload = [&](int kt) {
        #pragma unroll
        for (int i = 0; i < 4; i++) {
            int ch = tid + 256 * i;
            int r = ch >> 3, c8 = (ch & 7) * 8;
            cpa16(sptr(&Vh[r*SQa + c8]), &V_g[kvOff + (size_t)(kt + r) * DIMc + c8]);
        }
    };

    #pragma unroll
    for (int i = 0; i < 2; i++) {
        int ch = tid + 256 * i;
        int r = ch >> 3, c8 = (ch & 7) * 8;
        cpa16(sptr(&Qh[r*SQa + c8]), &Q_g[qOff + (size_t)r * DIMc + c8]);
    }
    kload(0, 0);
    cp_commit();

    const int wm = (warp & 3) * 16;     // m offset (16 rows per warp)
    const int wk = (warp >> 2) * 64;    // key-slice offset (64 keys per warp)

    float ctx[8][4];
    #pragma unroll
    for (int i = 0; i < 8; i++)
        #pragma unroll
        for (int j = 0; j < 4; j++) ctx[i][j] = 0.f;
    float rs0 = 0.f, rs1 = 0.f;

    // ---------------- pass 1 ----------------
    for (int t = 0; t < Sc / 128; t++) {
        const int cur = t & 1;
        const int kt = t * 128;
        cp_wait0();
        __syncthreads();                 // K_t visible; V slot free (prev PV done)
        vload(kt); cp_commit();          // group: V_t
        const bool pre = (t + 1 < Sc / 128);
        if (pre) { kload(cur ^ 1, kt + 128); cp_commit(); }   // group: K_{t+1}

        __half* KH = Kst + cur * KB;

        // scores: m16 x n64 per warp
        float s[8][4];
        #pragma unroll
        for (int i = 0; i < 8; i++)
            #pragma unroll
            for (int j = 0; j < 4; j++) s[i][j] = 0.f;
        #pragma unroll
        for (int kk = 0; kk < 64; kk += 16) {
            unsigned ah[4];
            ldsm4(sptr(Qh + (wm + (g & 1)*8 + r7)*SQa + kk + (g >> 1)*8), ah);
            #pragma unroll
            for (int np = 0; np < 4; np++) {
                unsigned bh[4];
                ldsm4(sptr(KH + (wk + np*16 + (g >> 1)*8 + r7)*SQa + kk + (g & 1)*8), bh);
                mma_f16(s[np*2],   ah, bh[0], bh[1]);
                mma_f16(s[np*2+1], ah, bh[2], bh[3]);
            }
        }

        if (pre) cp_wait1(); else cp_wait0();   // V_t arrived
        __syncthreads();                        // V visible to all warps

        // exp in place + rowsum partials
        #pragma unroll
        for (int nt = 0; nt < 8; nt++) {
            s[nt][0] = __expf(s[nt][0] * 0.125f);
            s[nt][1] = __expf(s[nt][1] * 0.125f);
            s[nt][2] = __expf(s[nt][2] * 0.125f);
            s[nt][3] = __expf(s[nt][3] * 0.125f);
            rs0 += s[nt][0] + s[nt][1];
            rs1 += s[nt][2] + s[nt][3];
        }

        // PV over this warp's 64-key slice: C-frag -> A-frag in registers
        #pragma unroll
        for (int kc = 0; kc < 4; kc++) {
            unsigned a[4];
            a[0] = packh2(s[kc*2][0],   s[kc*2][1]);
            a[1] = packh2(s[kc*2][2],   s[kc*2][3]);
            a[2] = packh2(s[kc*2+1][0], s[kc*2+1][1]);
            a[3] = packh2(s[kc*2+1][2], s[kc*2+1][3]);
            int vrow = wk + kc*16 + (g & 1)*8 + r7;
            #pragma unroll
            for (int dp = 0; dp < 4; dp++) {
                unsigned bh[4];
                ldsm4t(sptr(Vh + vrow*SQa + dp*16 + (g >> 1)*8), bh);
                mma_f16(ctx[dp*2],   a, bh[0], bh[1]);
                mma_f16(ctx[dp*2+1], a, bh[2], bh[3]);
            }
        }
    }

    // rowsum accumulation
    atomicAdd(&rowsum[wm + (lane >> 2)],     rs0);
    atomicAdd(&rowsum[wm + 8 + (lane >> 2)], rs1);
    __syncthreads();                      // PV done (Vh dead), atomics visible

    // invert rowsum; k-slice 0 warps write partials to red (aliases Vh)
    if (tid < 64) rowsum[tid] = 1.0f / rowsum[tid];
    if (warp < 4) {
        int r0 = wm + (lane >> 2);
        #pragma unroll
        for (int dt = 0; dt < 8; dt++) {
            int cc = dt*8 + (lane & 3)*2;
            red[r0*65 + cc]       = ctx[dt][0];
            red[r0*65 + cc + 1]   = ctx[dt][1];
            red[(r0+8)*65 + cc]   = ctx[dt][2];
            red[(r0+8)*65 + cc+1] = ctx[dt][3];
        }
    }
    __syncthreads();
    if (warp >= 4) {
        int r0 = wm + (lane >> 2);
        #pragma unroll
        for (int dt = 0; dt < 8; dt++) {
            int cc = dt*8 + (lane & 3)*2;
            red[r0*65 + cc]       += ctx[dt][0];
            red[r0*65 + cc + 1]   += ctx[dt][1];
            red[(r0+8)*65 + cc]   += ctx[dt][2];
            red[(r0+8)*65 + cc+1] += ctx[dt][3];
        }
    }
    __syncthreads();

    // prefetch pass-2 K_0 while we store ctx
    kload(0, 0); cp_commit();

    // normalize + store C (coalesced)
    #pragma unroll
    for (int i = 0; i < 8; i++) {
        int p = tid + 256 * i;            // 2048 h2 pairs: 64 rows x 32
        int row = p >> 5;
        int cc = (p & 31) * 2;
        float iv = rowsum[row];
        *(unsigned*)&C_g[qOff + (size_t)row * DIMc + cc] =
            packh2(red[row*65 + cc] * iv, red[row*65 + cc + 1] * iv);
    }

    const float iv0 = rowsum[wm + (lane >> 2)];
    const float iv1 = rowsum[wm + 8 + (lane >> 2)];
    __syncthreads();   // red/rowsum reads done before pass 2

    // ---------------- pass 2: recompute scores, write normalized ----------
    for (int t = 0; t < Sc / 128; t++) {
        const int cur = t & 1;
        const int kt = t * 128;
        cp_wait0();
        __syncthreads();
        if (t + 1 < Sc / 128) { kload(cur ^ 1, kt + 128); cp_commit(); }

        __half* KH = Kst + cur * KB;

        float s[8][4];
        #pragma unroll
        for (int i = 0; i < 8; i++)
            #pragma unroll
            for (int j = 0; j < 4; j++) s[i][j] = 0.f;
        #pragma unroll
        for (int kk = 0; kk < 64; kk += 16) {
            unsigned ah[4];
            ldsm4(sptr(Qh + (wm + (g & 1)*8 + r7)*SQa + kk + (g >> 1)*8), ah);
            #pragma unroll
            for (int np = 0; np < 4; np++) {
                unsigned bh[4];
                ldsm4(sptr(KH + (wk + np*16 + (g >> 1)*8 + r7)*SQa + kk + (g & 1)*8), bh);
                mma_f16(s[np*2],   ah, bh[0], bh[1]);
                mma_f16(s[np*2+1], ah, bh[2], bh[3]);
            }
        }

        int row0 = wm + (lane >> 2);
        #pragma unroll
        for (int nt = 0; nt < 8; nt++) {
            int col = wk + nt*8 + (lane & 3)*2;
            float e0 = __expf(s[nt][0] * 0.125f) * iv0;
            float e1 = __expf(s[nt][1] * 0.125f) * iv0;
            float e2 = __expf(s[nt][2] * 0.125f) * iv1;
            float e3 = __expf(s[nt][3] * 0.125f) * iv1;
            *(float2*)(arow + (size_t)row0 * Sc + kt + col)     = make_float2(e0, e1);
            *(float2*)(arow + (size_t)(row0+8) * Sc + kt + col) = make_float2(e2, e3);
        }
    }
}

// ---------------------------------------------------------------------------
// Launcher
// ---------------------------------------------------------------------------
extern "C" void kernel_launch(void* const* d_in, const int* in_sizes, int n_in,
                              void* d_out, int out_size)
{
    const float* x  = (const float*)d_in[0];
    const float* wq = (const float*)d_in[1];
    const float* wk = (const float*)d_in[2];
    const float* wv = (const float*)d_in[3];
    const float* wo = (const float*)d_in[4];
    const float* fc = (const float*)d_in[5];
    const float* fs = (const float*)d_in[6];

    float* out  = (float*)d_out;
    float* attn = out + (size_t)Bc * Sc * DIMc;

    __half* buf;
    cudaGetSymbolAddress((void**)&buf, g_buf);
    const size_t WM = (size_t)DIMc * DIMc;
    __half* X = buf;
    __half* W = buf + 1ull*CHUNK;
    __half* Q = buf + 2ull*CHUNK;    // Q,K,V contiguous (z-indexed)
    __half* C = buf + 5ull*CHUNK;

    const int projSmem = 3 * 2 * PBUFp * 2;                 // 110,592 B
    cudaFuncSetAttribute(proj_mma<0>, cudaFuncAttributeMaxDynamicSharedMemorySize, projSmem);
    cudaFuncSetAttribute(proj_mma<1>, cudaFuncAttributeMaxDynamicSharedMemorySize, projSmem);
    const int attnSmem = (QB64 + 3*KB) * 2 + 64 * 4;        // 64,768 B
    cudaFuncSetAttribute(attn_mma, cudaFuncAttributeMaxDynamicSharedMemorySize, attnSmem);

    int nCvt = CHUNK / 4 + DIMc * DIMc;
    cvt_all<<<(nCvt + 255) / 256, 256>>>(x, wq, wk, wv, wo, X, W);

    // fused QKV (z=0 Q rope, z=1 K rope, z=2 V)
    proj_mma<1><<<dim3(DIMc/128, TTOT/128, 3), 256, projSmem>>>(X, W, nullptr, Q, fc, fs);

    attn_mma<<<dim3(Sc/64, NHc, Bc), 256, attnSmem>>>(attn, Q, Q + 1ull*CHUNK, Q + 2ull*CHUNK, C);

    proj_mma<0><<<dim3(DIMc/128, TTOT/128, 1), 256, projSmem>>>(C, W + 3*WM, out, nullptr, nullptr, nullptr);
}